// round 4
// baseline (speedup 1.0000x reference)
#include <cuda_runtime.h>

#define NPW      2048      // 65536 points / 32 bits (words per scene row)
#define PTOT_MAX 512
#define BMAX     8
#define MAXP     128
#define CAP      16384     // bucket capacity per proposal (expected max ~8.2k)
#define CNTPAD   32        // pad counters to 128B so each lands on its own L2 slice

__device__ unsigned g_pc_bits[PTOT_MAX * NPW];   // 4 MB overflow-fallback bitmask
__device__ unsigned g_ref_bits[BMAX * NPW];      // per-scene reference bitmask
__device__ int      g_offs[BMAX + 1];
__device__ float    g_iou[PTOT_MAX];
__device__ int      g_cnt[PTOT_MAX * CNTPAD];    // padded per-proposal counters
__device__ int      g_bucket[PTOT_MAX * CAP];    // 32 MB: j-values grouped by proposal
__device__ int      g_ctr;

// ---- K1: offsets + counter zero + reference bitmask (warp ballot) ----
__global__ void k_init(const int* __restrict__ labels, const int* __restrict__ object_id,
                       const int* __restrict__ pes, int B, int npoint, int n_total,
                       int shift /* log2(npoint) if pow2 else -1 */) {
    int i = blockIdx.x * blockDim.x + threadIdx.x;
    if (i == 0) {
        g_offs[0] = 0;
        for (int b = 0; b < B; b++) g_offs[b + 1] = g_offs[b] + __ldg(&pes[b]);
        g_ctr = 0;
    }
    if (i < PTOT_MAX) g_cnt[i * CNTPAD] = 0;
    if (i >= n_total) return;
    int b = (shift >= 0) ? (i >> shift) : (i / npoint);
    int oid = __ldg(&object_id[b]);
    unsigned bits = __ballot_sync(0xffffffffu, __ldg(&labels[i]) == oid);
    if ((threadIdx.x & 31) == 0) {
        int jl = i - b * npoint;                 // local point index (warp-aligned: npoint%32==0)
        g_ref_bits[b * NPW + (jl >> 5)] = bits;
    }
}

// ---- K2: bin pairs by proposal (plain stores, no RMW) ----
template <bool POW2>
__global__ void k_bin(const int4* __restrict__ pidx2, int M2, unsigned npoint, unsigned mask) {
    int i = blockIdx.x * blockDim.x + threadIdx.x;
    if (i >= M2) return;
    int4 a = __ldg(&pidx2[i]);                       // two (pid, j) pairs
    unsigned j0 = POW2 ? ((unsigned)a.y & mask) : ((unsigned)a.y % npoint);
    unsigned j1 = POW2 ? ((unsigned)a.w & mask) : ((unsigned)a.w % npoint);
    int s0 = atomicAdd(&g_cnt[a.x * CNTPAD], 1);
    if (s0 < CAP) g_bucket[a.x * CAP + s0] = (int)j0;
    else atomicOr(&g_pc_bits[(size_t)a.x * NPW + (j0 >> 5)], 1u << (j0 & 31u));
    int s1 = atomicAdd(&g_cnt[a.z * CNTPAD], 1);
    if (s1 < CAP) g_bucket[a.z * CAP + s1] = (int)j1;
    else atomicOr(&g_pc_bits[(size_t)a.z * NPW + (j1 >> 5)], 1u << (j1 & 31u));
}

__global__ void k_bin_tail(const int2* __restrict__ pidx, int start, int M, unsigned npoint) {
    int i = start + blockIdx.x * blockDim.x + threadIdx.x;
    if (i >= M) return;
    int2 v = __ldg(&pidx[i]);
    unsigned j = (unsigned)v.y % npoint;
    int s = atomicAdd(&g_cnt[v.x * CNTPAD], 1);
    if (s < CAP) g_bucket[v.x * CAP + s] = (int)j;
    else atomicOr(&g_pc_bits[(size_t)v.x * NPW + (j >> 5)], 1u << (j & 31u));
}

// ---- K3: one CTA per proposal — SMEM bitmask dedup + popcount + IoU,
//          then last-block-done epilogue writes all outputs.
// Output layout (f32): [B*MAXP*C clus_feats | B*C select_feats | B sel_idx | B+1 offsets | B good]
__global__ void k_proposal(int B, int npw, int PTOT, int C,
                           const float* __restrict__ feats,
                           const int* __restrict__ pes,
                           float* __restrict__ out) {
    __shared__ unsigned bm[NPW];                    // 8 KB bitmask
    int p = blockIdx.x;
    int tid = threadIdx.x;

    #pragma unroll
    for (int w = tid; w < NPW; w += 256) bm[w] = 0u;
    __syncthreads();

    int ct = g_cnt[p * CNTPAD];
    int n = ct < CAP ? ct : CAP;
    const int* __restrict__ bk = g_bucket + (size_t)p * CAP;
    for (int idx = tid; idx < n; idx += 256) {
        unsigned j = (unsigned)__ldg(&bk[idx]);
        atomicOr(&bm[j >> 5], 1u << (j & 31u));
    }
    __syncthreads();
    if (ct > CAP) {                                 // overflow fallback (normally never)
        for (int w = tid; w < npw; w += 256)
            bm[w] |= g_pc_bits[(size_t)p * NPW + w];
        __syncthreads();
    }

    // scene id of this proposal
    int b = 0;
    #pragma unroll
    for (int k = 1; k <= BMAX; k++) b += (k <= B && g_offs[k] <= p) ? 1 : 0;
    if (b >= B) b = B - 1;

    // popcount: |pc|, |pc & ref|, |ref|
    const uint4* __restrict__ ref4 = (const uint4*)(g_ref_bits + (size_t)b * NPW);
    const uint4* __restrict__ bm4  = (const uint4*)bm;
    int nq = npw >> 2;
    unsigned cnt = 0, its = 0, rs = 0;
    for (int w = tid; w < nq; w += 256) {
        uint4 v = bm4[w];
        uint4 r = __ldg(&ref4[w]);
        cnt += __popc(v.x) + __popc(v.y) + __popc(v.z) + __popc(v.w);
        its += __popc(v.x & r.x) + __popc(v.y & r.y)
             + __popc(v.z & r.z) + __popc(v.w & r.w);
        rs  += __popc(r.x) + __popc(r.y) + __popc(r.z) + __popc(r.w);
    }
    cnt = __reduce_add_sync(0xffffffffu, cnt);
    its = __reduce_add_sync(0xffffffffu, its);
    rs  = __reduce_add_sync(0xffffffffu, rs);
    __shared__ unsigned sc[8], si[8], sr[8];
    int warp = tid >> 5;
    if ((tid & 31) == 0) { sc[warp] = cnt; si[warp] = its; sr[warp] = rs; }
    __syncthreads();
    if (tid == 0) {
        unsigned Ct = 0, It = 0, Rt = 0;
        #pragma unroll
        for (int w = 0; w < 8; w++) { Ct += sc[w]; It += si[w]; Rt += sr[w]; }
        float inter = (float)It;
        float uni = (float)Ct + (float)Rt - inter;
        g_iou[p] = (uni > 0.0f) ? inter / fmaxf(uni, 1.0f) : 0.0f;
    }

    // ---- last-block-done epilogue ----
    __syncthreads();
    __shared__ int s_last;
    if (tid == 0) {
        __threadfence();
        s_last = (atomicAdd(&g_ctr, 1) == (int)gridDim.x - 1) ? 1 : 0;
    }
    __syncthreads();
    if (!s_last) return;

    __shared__ int   s_best[BMAX];
    __shared__ float s_max[BMAX];
    if (tid < B) {
        int lo = g_offs[tid], hi = g_offs[tid + 1];
        int best = -1; float mx = -1.0f;
        for (int p2 = lo; p2 < hi; p2++) {
            float v = g_iou[p2];
            if (v > mx) { mx = v; best = p2; }   // strict >: first max wins
        }
        s_best[tid] = (__ldg(&pes[tid]) > 0) ? best : -1;
        s_max[tid] = mx;
    }
    __syncthreads();
    int clus_n   = B * MAXP * C;
    int sf_off   = clus_n;
    int spi_off  = sf_off + B * C;
    int offs_off = spi_off + B;
    int good_off = offs_off + B + 1;
    int mc = MAXP * C;
    for (int idx = tid; idx < clus_n; idx += 256) {
        int b2 = idx / mc, rem = idx - b2 * mc;
        int slot = rem / C, c = rem - slot * C;
        int pp = g_offs[b2] + slot;
        out[idx] = (pp < g_offs[b2 + 1]) ? __ldg(&feats[(size_t)pp * C + c]) : 0.0f;
    }
    for (int idx = tid; idx < B * C; idx += 256) {
        int b2 = idx / C, c = idx - b2 * C;
        int sel = s_best[b2];
        out[sf_off + idx] = (sel >= 0) ? __ldg(&feats[(size_t)sel * C + c]) : 0.0f;
    }
    if (tid < B)  out[spi_off + tid]  = (float)s_best[tid];
    if (tid <= B) out[offs_off + tid] = (float)g_offs[tid];
    if (tid < B)  out[good_off + tid] = ((s_max[tid] > 0.2f) && (__ldg(&pes[tid]) > 0)) ? 1.0f : 0.0f;
}

extern "C" void kernel_launch(void* const* d_in, const int* in_sizes, int n_in,
                              void* d_out, int out_size) {
    const int*   pidx   = (const int*)d_in[0];   // [M,2] int32
    const int*   pes    = (const int*)d_in[1];   // [B] int32
    const int*   labels = (const int*)d_in[2];   // [B*npoint] int32
    const int*   oid    = (const int*)d_in[3];   // [B] int32
    const float* feats  = (const float*)d_in[4]; // [PTOT, C] f32
    float* out = (float*)d_out;

    int M       = in_sizes[0] / 2;
    int B       = in_sizes[1];
    int n_total = in_sizes[2];
    int npoint  = n_total / B;
    int C       = 32;
    int PTOT    = in_sizes[4] / C;
    int npw     = (npoint + 31) / 32;

    bool pow2 = (npoint & (npoint - 1)) == 0;
    int shift = -1;
    if (pow2) { shift = 0; while ((1 << shift) < npoint) shift++; }

    // zero the overflow-fallback bitmask (only consumed when a bucket overflows)
    void* pc_ptr = nullptr;
    cudaGetSymbolAddress(&pc_ptr, g_pc_bits);
    cudaMemsetAsync(pc_ptr, 0, (size_t)PTOT * NPW * sizeof(unsigned), 0);

    k_init<<<(n_total + 255) / 256, 256>>>(labels, oid, pes, B, npoint, n_total, shift);

    int M2 = M / 2;
    if (M2 > 0) {
        if (pow2)
            k_bin<true><<<(M2 + 255) / 256, 256>>>((const int4*)pidx, M2,
                                                   (unsigned)npoint, (unsigned)(npoint - 1));
        else
            k_bin<false><<<(M2 + 255) / 256, 256>>>((const int4*)pidx, M2,
                                                    (unsigned)npoint, (unsigned)(npoint - 1));
    }
    if (M & 1)
        k_bin_tail<<<1, 32>>>((const int2*)pidx, M2 * 2, M, (unsigned)npoint);

    k_proposal<<<PTOT, 256>>>(B, npw, PTOT, C, feats, pes, out);
}

// round 6
// speedup vs baseline: 2.1741x; 2.1741x over previous
#include <cuda_runtime.h>

#define NPW      2048      // 65536 points / 32 bits (words per proposal row)
#define PTOT_MAX 512
#define BMAX     8
#define MAXP     128

__device__ unsigned g_pc_bits[PTOT_MAX * NPW];   // 4 MB bitmask; zeroed-on-read by k_reduce
__device__ unsigned g_ref_bits[BMAX * NPW];      // per-scene reference bitmask (fully rewritten)
__device__ int      g_offs[BMAX + 1];
__device__ float    g_iou[PTOT_MAX];
__device__ int      g_ctr;

// ---- Kernel A: scatter (2 pairs/thread, RED.OR) + ref ballot init + offsets ----
__global__ void __launch_bounds__(256, 8)
k_main(const int4* __restrict__ pidx2, const int2* __restrict__ pidx,
       const int* __restrict__ labels, const int* __restrict__ object_id,
       const int* __restrict__ pes,
       int M, int M2, int B, int npoint, int n_total, unsigned npu) {
    int t = blockIdx.x * blockDim.x + threadIdx.x;

    if (t == 0) {
        g_offs[0] = 0;
        for (int b = 0; b < B; b++) g_offs[b + 1] = g_offs[b] + __ldg(&pes[b]);
        g_ctr = 0;
    }

    // --- reference bitmask via warp ballot (one label per thread) ---
    if (t < n_total) {
        int b = t / npoint;
        int oid = __ldg(&object_id[b]);
        int jl = t - b * npoint;
        unsigned wbase = (unsigned)(t & ~31);
        if (wbase + 32 <= (unsigned)n_total) {        // full warp, same scene (npoint%32==0)
            unsigned bits = __ballot_sync(0xffffffffu, __ldg(&labels[t]) == oid);
            if ((t & 31) == 0) g_ref_bits[b * NPW + (jl >> 5)] = bits;
        } else {                                      // ragged tail fallback
            if (__ldg(&labels[t]) == oid)
                atomicOr(&g_ref_bits[b * NPW + (jl >> 5)], 1u << (jl & 31u));
        }
    }

    // --- scatter: set bit (pid, j % npoint) ---
    if (t < M2) {
        int4 a = __ldg(&pidx2[t]);                    // two (pid, j) pairs
        unsigned j0 = (unsigned)a.y % npu;
        unsigned j1 = (unsigned)a.w % npu;
        atomicOr(&g_pc_bits[(size_t)a.x * NPW + (j0 >> 5)], 1u << (j0 & 31u));
        atomicOr(&g_pc_bits[(size_t)a.z * NPW + (j1 >> 5)], 1u << (j1 & 31u));
    }
    if ((M & 1) && t == M2) {                         // odd tail pair
        int2 v = __ldg(&pidx[M - 1]);
        unsigned j = (unsigned)v.y % npu;
        atomicOr(&g_pc_bits[(size_t)v.x * NPW + (j >> 5)], 1u << (j & 31u));
    }
}

// ---- Kernel B: warp-per-proposal AND-popcount (uint4, MLP=16) + zero-on-read,
//      then last-block-done epilogue writes all outputs.
// Output layout (f32): [B*MAXP*C clus_feats | B*C select_feats | B sel_idx | B+1 offsets | B good]
__global__ void __launch_bounds__(256, 8)
k_reduce_final(int B, int npw, int PTOT, int C,
               const float* __restrict__ feats,
               const int* __restrict__ pes,
               float* __restrict__ out) {
    int lane = threadIdx.x & 31;
    int gw = (blockIdx.x * blockDim.x + threadIdx.x) >> 5;  // proposal id
    if (gw < PTOT) {
        int p = gw;
        int b = 0;
        #pragma unroll
        for (int k = 1; k <= BMAX; k++) b += (k <= B && g_offs[k] <= p) ? 1 : 0;
        if (b >= B) b = B - 1;
        uint4* pcrow = (uint4*)(g_pc_bits + (size_t)p * NPW);
        const uint4* __restrict__ refrow = (const uint4*)(g_ref_bits + (size_t)b * NPW);
        int nq = npw >> 2;                 // uint4 chunks per row
        unsigned cnt = 0, its = 0, rs = 0;
        const uint4 z = make_uint4(0u, 0u, 0u, 0u);
        #pragma unroll 16
        for (int w = lane; w < nq; w += 32) {
            uint4 v = pcrow[w];
            uint4 r = __ldg(&refrow[w]);
            pcrow[w] = z;                              // self-clean for next replay
            cnt += __popc(v.x) + __popc(v.y) + __popc(v.z) + __popc(v.w);
            its += __popc(v.x & r.x) + __popc(v.y & r.y)
                 + __popc(v.z & r.z) + __popc(v.w & r.w);
            rs  += __popc(r.x) + __popc(r.y) + __popc(r.z) + __popc(r.w);
        }
        cnt = __reduce_add_sync(0xffffffffu, cnt);
        its = __reduce_add_sync(0xffffffffu, its);
        rs  = __reduce_add_sync(0xffffffffu, rs);
        if (lane == 0) {
            float inter = (float)its;
            float uni = (float)cnt + (float)rs - inter;
            g_iou[p] = (uni > 0.0f) ? inter / fmaxf(uni, 1.0f) : 0.0f;
        }
    }
    // ---- last-block-done epilogue ----
    __syncthreads();
    __shared__ int s_last;
    if (threadIdx.x == 0) {
        __threadfence();
        s_last = (atomicAdd(&g_ctr, 1) == (int)gridDim.x - 1) ? 1 : 0;
    }
    __syncthreads();
    if (!s_last) return;

    __shared__ int   s_best[BMAX];
    __shared__ float s_max[BMAX];
    int tid = threadIdx.x;
    if (tid < B) {
        int lo = g_offs[tid], hi = g_offs[tid + 1];
        int best = -1; float mx = -1.0f;
        for (int p2 = lo; p2 < hi; p2++) {
            float v = g_iou[p2];
            if (v > mx) { mx = v; best = p2; }    // strict >: first max wins
        }
        s_best[tid] = (__ldg(&pes[tid]) > 0) ? best : -1;
        s_max[tid] = mx;
    }
    __syncthreads();
    int clus_n   = B * MAXP * C;
    int sf_off   = clus_n;
    int spi_off  = sf_off + B * C;
    int offs_off = spi_off + B;
    int good_off = offs_off + B + 1;
    int mc = MAXP * C;
    for (int idx = tid; idx < clus_n; idx += blockDim.x) {
        int b2 = idx / mc, rem = idx - b2 * mc;
        int slot = rem / C, c = rem - slot * C;
        int pp = g_offs[b2] + slot;
        out[idx] = (pp < g_offs[b2 + 1]) ? __ldg(&feats[(size_t)pp * C + c]) : 0.0f;
    }
    for (int idx = tid; idx < B * C; idx += blockDim.x) {
        int b2 = idx / C, c = idx - b2 * C;
        int sel = s_best[b2];
        out[sf_off + idx] = (sel >= 0) ? __ldg(&feats[(size_t)sel * C + c]) : 0.0f;
    }
    if (tid < B)  out[spi_off + tid]  = (float)s_best[tid];
    if (tid <= B) out[offs_off + tid] = (float)g_offs[tid];
    if (tid < B)  out[good_off + tid] = ((s_max[tid] > 0.2f) && (__ldg(&pes[tid]) > 0)) ? 1.0f : 0.0f;
}

extern "C" void kernel_launch(void* const* d_in, const int* in_sizes, int n_in,
                              void* d_out, int out_size) {
    const int*   pidx   = (const int*)d_in[0];   // [M,2] int32
    const int*   pes    = (const int*)d_in[1];   // [B] int32
    const int*   labels = (const int*)d_in[2];   // [B*npoint] int32
    const int*   oid    = (const int*)d_in[3];   // [B] int32
    const float* feats  = (const float*)d_in[4]; // [PTOT, C] f32
    float* out = (float*)d_out;

    int M       = in_sizes[0] / 2;
    int B       = in_sizes[1];
    int n_total = in_sizes[2];
    int npoint  = n_total / B;
    int C       = 32;
    int PTOT    = in_sizes[4] / C;
    int npw     = (npoint + 31) / 32;

    int M2 = M / 2;
    int workA = M2 + 1;                       // +1 covers the odd-tail thread
    if (workA < n_total) workA = n_total;
    int gridA = (workA + 255) / 256;
    k_main<<<gridA, 256>>>((const int4*)pidx, (const int2*)pidx, labels, oid, pes,
                           M, M2, B, npoint, n_total, (unsigned)npoint);

    int gridB = (PTOT * 32 + 255) / 256;      // one warp per proposal
    k_reduce_final<<<gridB, 256>>>(B, npw, PTOT, C, feats, pes, out);
}